// round 1
// baseline (speedup 1.0000x reference)
#include <cuda_runtime.h>
#include <cuda_bf16.h>
#include <cstdint>

// Problem constants
#define BB 64
#define SS 2048
#define II 64
#define HH 128

// Scratch (allocation-free rule: __device__ globals)
__device__ float g_wx[BB * SS * HH];    // wx0, then reused as wx1
__device__ float g_out0[BB * SS * HH];  // layer-0 output (intermediate only)

// ---------------- f32x2 helpers ----------------
__device__ __forceinline__ unsigned long long pk2(float lo, float hi) {
    unsigned long long r;
    asm("mov.b64 %0, {%1,%2};" : "=l"(r) : "f"(lo), "f"(hi));
    return r;
}
__device__ __forceinline__ unsigned long long ffma2(unsigned long long a,
                                                    unsigned long long b,
                                                    unsigned long long c) {
    unsigned long long d;
    asm("fma.rn.f32x2 %0, %1, %2, %3;" : "=l"(d) : "l"(a), "l"(b), "l"(c));
    return d;
}
__device__ __forceinline__ float2 up2(unsigned long long v) {
    float2 f;
    asm("mov.b64 {%0,%1}, %2;" : "=f"(f.x), "=f"(f.y) : "l"(v));
    return f;
}

__device__ __forceinline__ float sigmoidf_(float x) {
    return __fdividef(1.0f, 1.0f + __expf(-x));
}
__device__ __forceinline__ float tanhf_(float x) {
    // tanh(x) = 1 - 2/(exp(2x)+1); robust at both extremes with __expf
    return 1.0f - __fdividef(2.0f, __expf(2.0f * x) + 1.0f);
}

// ---------------- GEMM: Out[M,128] = A[M,K] @ W[K,128] into g_wx ----------------
// Tile: 64 rows x 128 cols per CTA of 128 threads.
// Thread t: column pair cp = t & 63 (cols 2cp,2cp+1), row half rh = t >> 6 (32 rows).
// A staged in SMEM as duplicated f32x2 pairs so the inner loop is pure LDS+FFMA2.
template <int K, bool SRC_SCRATCH>
__global__ __launch_bounds__(128) void gemm_proj(const float* __restrict__ Ain,
                                                 const float* __restrict__ W) {
    const float* __restrict__ A = SRC_SCRATCH ? (const float*)g_out0 : Ain;
    constexpr int KC = 32;
    __shared__ unsigned long long ATd[KC][66];  // [k][row] duplicated pairs, padded pitch (even)
    __shared__ float Wsh[KC][HH];

    const int tid = threadIdx.x;
    const int row0 = blockIdx.x * 64;
    const int cp = tid & 63;
    const int rh = tid >> 6;

    unsigned long long acc[32];
#pragma unroll
    for (int i = 0; i < 32; i++) acc[i] = 0ULL;  // bit pattern of (0.f,0.f)

    for (int k0 = 0; k0 < K; k0 += KC) {
        // Stage A chunk (coalesced over k), duplicated
#pragma unroll
        for (int i = 0; i < 16; i++) {
            int idx = tid + i * 128;          // 64*32 = 2048 elements
            int r = idx >> 5, k = idx & 31;   // consecutive tid -> consecutive k
            float a = A[(size_t)(row0 + r) * K + (k0 + k)];
            ATd[k][r] = pk2(a, a);
        }
        // Stage W chunk (coalesced over c)
#pragma unroll
        for (int i = 0; i < 32; i++) {
            int idx = tid + i * 128;          // 32*128 = 4096
            int k = idx >> 7, c = idx & 127;
            Wsh[k][c] = W[(size_t)(k0 + k) * HH + c];
        }
        __syncthreads();

#pragma unroll 4
        for (int k = 0; k < KC; k++) {
            float2 wv = *(const float2*)&Wsh[k][2 * cp];
            unsigned long long w2 = pk2(wv.x, wv.y);
            const unsigned long long* arow = &ATd[k][rh * 32];
#pragma unroll
            for (int rr = 0; rr < 16; rr++) {
                ulonglong2 av = *(const ulonglong2*)(arow + 2 * rr);
                acc[2 * rr]     = ffma2(av.x, w2, acc[2 * rr]);
                acc[2 * rr + 1] = ffma2(av.y, w2, acc[2 * rr + 1]);
            }
        }
        __syncthreads();
    }

#pragma unroll
    for (int r = 0; r < 32; r++) {
        float2 v = up2(acc[r]);
        *(float2*)&g_wx[(size_t)(row0 + rh * 32 + r) * HH + 2 * cp] = v;
    }
}

// ---------------- Recurrence kernel ----------------
// One CTA per batch element, 128 threads (thread j owns output channel j).
// u column j lives in 64 packed f32x2 registers; h double-buffered in SMEM
// (one __syncthreads per step). wx prefetched one step ahead.
// LAYER==0: reads g_wx (wx0), writes g_out0.  LAYER==1: reads g_wx (wx1), writes d_out.
template <int LAYER>
__global__ __launch_bounds__(128) void recurrence_k(
    const float* __restrict__ u, const float* __restrict__ bg,
    const float* __restrict__ bu, const float* __restrict__ zeta,
    const float* __restrict__ nu, const float* __restrict__ lambd,
    const float* __restrict__ gamma, float* __restrict__ d_out_full,
    int write_h) {
    const int b = blockIdx.x;
    const int j = threadIdx.x;

    __shared__ __align__(16) float h_sh[2][HH];

    // u column -> 64 packed (u[2m][j], u[2m+1][j]) register pairs
    unsigned long long ucp[64];
#pragma unroll
    for (int m = 0; m < 64; m++)
        ucp[m] = pk2(u[(size_t)(2 * m) * HH + j], u[(size_t)(2 * m + 1) * HH + j]);

    const float bgj = bg[j];
    const float buj = bu[j];
    const float sz = sigmoidf_(zeta[0]);
    const float sn = sigmoidf_(nu[0]);
    const float gcv = fminf(fmaxf(gamma[0], 0.0f), 1.0f);
    const float c1 = (1.0f - gcv) * lambd[0];

    h_sh[0][j] = 0.0f;
    float h_prev = 0.0f;

    const float* __restrict__ wx = g_wx + (size_t)b * SS * HH + j;
    float* __restrict__ outp =
        (LAYER == 0) ? (g_out0 + (size_t)b * SS * HH + j)
                     : (d_out_full + (size_t)b * SS * HH + j);

    __syncthreads();
    float wx_cur = wx[0];

    for (int t = 0; t < SS; t++) {
        // prefetch next step's wx early (hidden behind the matvec)
        int tn = (t + 1 < SS) ? (t + 1) : (SS - 1);
        float wx_nxt = wx[(size_t)tn * HH];

        const float* hb = h_sh[t & 1];
        unsigned long long a0 = 0ULL, a1 = 0ULL, a2 = 0ULL, a3 = 0ULL;
#pragma unroll
        for (int m = 0; m < 16; m++) {
            float4 hA = *(const float4*)(hb + 8 * m);
            float4 hB = *(const float4*)(hb + 8 * m + 4);
            a0 = ffma2(pk2(hA.x, hA.y), ucp[4 * m + 0], a0);
            a1 = ffma2(pk2(hA.z, hA.w), ucp[4 * m + 1], a1);
            a2 = ffma2(pk2(hB.x, hB.y), ucp[4 * m + 2], a2);
            a3 = ffma2(pk2(hB.z, hB.w), ucp[4 * m + 3], a3);
        }
        float2 s0 = up2(a0), s1 = up2(a1), s2 = up2(a2), s3 = up2(a3);
        float pre = ((s0.x + s0.y) + (s1.x + s1.y)) +
                    ((s2.x + s2.y) + (s3.x + s3.y)) + wx_cur;

        float z = sigmoidf_(pre + bgj);
        float hh = tanhf_(pre + buj);
        float h_new = z * h_prev + (sz * (1.0f - z) + sn) * hh;
        float ho = gcv * h_new + c1;

        outp[(size_t)t * HH] = ho;
        h_prev = ho;
        h_sh[(t + 1) & 1][j] = ho;
        __syncthreads();
        wx_cur = wx_nxt;
    }

    if (write_h) {
        d_out_full[(size_t)BB * SS * HH + (size_t)LAYER * BB * HH + b * HH + j] =
            h_prev;
    }
}

// ---------------- launch ----------------
extern "C" void kernel_launch(void* const* d_in, const int* in_sizes, int n_in,
                              void* d_out, int out_size) {
    const float* x      = (const float*)d_in[0];
    const float* w0     = (const float*)d_in[1];
    const float* u0     = (const float*)d_in[2];
    const float* bg0    = (const float*)d_in[3];
    const float* bu0    = (const float*)d_in[4];
    const float* zeta0  = (const float*)d_in[5];
    const float* nu0    = (const float*)d_in[6];
    const float* lambd0 = (const float*)d_in[7];
    const float* gamma0 = (const float*)d_in[8];
    const float* w1     = (const float*)d_in[9];
    const float* u1     = (const float*)d_in[10];
    const float* bg1    = (const float*)d_in[11];
    const float* bu1    = (const float*)d_in[12];
    const float* zeta1  = (const float*)d_in[13];
    const float* nu1    = (const float*)d_in[14];
    const float* lambd1 = (const float*)d_in[15];
    const float* gamma1 = (const float*)d_in[16];

    float* out = (float*)d_out;
    const int M = BB * SS;
    const int write_h = (out_size >= BB * SS * HH + 2 * BB * HH) ? 1 : 0;

    // wx0 = x @ w0
    gemm_proj<II, false><<<M / 64, 128>>>(x, w0);
    // layer 0 recurrence -> g_out0 (+ h0T)
    recurrence_k<0><<<BB, 128>>>(u0, bg0, bu0, zeta0, nu0, lambd0, gamma0, out,
                                 write_h);
    // wx1 = out0 @ w1
    gemm_proj<HH, true><<<M / 64, 128>>>(nullptr, w1);
    // layer 1 recurrence -> out (+ h1T)
    recurrence_k<1><<<BB, 128>>>(u1, bg1, bu1, zeta1, nu1, lambd1, gamma1, out,
                                 write_h);
}

// round 2
// speedup vs baseline: 1.0313x; 1.0313x over previous
#include <cuda_runtime.h>
#include <cuda_bf16.h>
#include <cstdint>

// Problem constants
#define BB 64
#define SS 2048
#define II 64
#define HH 128

// Scratch (allocation-free rule: __device__ globals)
__device__ float g_wx[BB * SS * HH];    // wx0, then reused as wx1
__device__ float g_out0[BB * SS * HH];  // layer-0 output (intermediate only)

// ---------------- f32x2 helpers ----------------
__device__ __forceinline__ unsigned long long pk2(float lo, float hi) {
    unsigned long long r;
    asm("mov.b64 %0, {%1,%2};" : "=l"(r) : "f"(lo), "f"(hi));
    return r;
}
__device__ __forceinline__ unsigned long long ffma2(unsigned long long a,
                                                    unsigned long long b,
                                                    unsigned long long c) {
    unsigned long long d;
    asm("fma.rn.f32x2 %0, %1, %2, %3;" : "=l"(d) : "l"(a), "l"(b), "l"(c));
    return d;
}
__device__ __forceinline__ unsigned long long addx2(unsigned long long a,
                                                    unsigned long long b) {
    unsigned long long d;
    asm("add.rn.f32x2 %0, %1, %2;" : "=l"(d) : "l"(a), "l"(b));
    return d;
}
__device__ __forceinline__ float2 up2(unsigned long long v) {
    float2 f;
    asm("mov.b64 {%0,%1}, %2;" : "=f"(f.x), "=f"(f.y) : "l"(v));
    return f;
}

__device__ __forceinline__ float sigmoidf_(float x) {
    return __fdividef(1.0f, 1.0f + __expf(-x));
}
__device__ __forceinline__ float tanhf_(float x) {
    // tanh(x) = 1 - 2/(exp(2x)+1); robust at both extremes with __expf
    return 1.0f - __fdividef(2.0f, __expf(2.0f * x) + 1.0f);
}

// ---------------- GEMM: Out[M,128] = A[M,K] @ W[K,128] into g_wx ----------------
// Tile: 64 rows x 128 cols per CTA of 128 threads.
template <int K, bool SRC_SCRATCH>
__global__ __launch_bounds__(128) void gemm_proj(const float* __restrict__ Ain,
                                                 const float* __restrict__ W) {
    const float* __restrict__ A = SRC_SCRATCH ? (const float*)g_out0 : Ain;
    constexpr int KC = 32;
    __shared__ unsigned long long ATd[KC][66];  // [k][row] duplicated pairs
    __shared__ float Wsh[KC][HH];

    const int tid = threadIdx.x;
    const int row0 = blockIdx.x * 64;
    const int cp = tid & 63;
    const int rh = tid >> 6;

    unsigned long long acc[32];
#pragma unroll
    for (int i = 0; i < 32; i++) acc[i] = 0ULL;

    for (int k0 = 0; k0 < K; k0 += KC) {
#pragma unroll
        for (int i = 0; i < 16; i++) {
            int idx = tid + i * 128;
            int r = idx >> 5, k = idx & 31;
            float a = A[(size_t)(row0 + r) * K + (k0 + k)];
            ATd[k][r] = pk2(a, a);
        }
#pragma unroll
        for (int i = 0; i < 32; i++) {
            int idx = tid + i * 128;
            int k = idx >> 7, c = idx & 127;
            Wsh[k][c] = W[(size_t)(k0 + k) * HH + c];
        }
        __syncthreads();

#pragma unroll 4
        for (int k = 0; k < KC; k++) {
            float2 wv = *(const float2*)&Wsh[k][2 * cp];
            unsigned long long w2 = pk2(wv.x, wv.y);
            const unsigned long long* arow = &ATd[k][rh * 32];
#pragma unroll
            for (int rr = 0; rr < 16; rr++) {
                ulonglong2 av = *(const ulonglong2*)(arow + 2 * rr);
                acc[2 * rr]     = ffma2(av.x, w2, acc[2 * rr]);
                acc[2 * rr + 1] = ffma2(av.y, w2, acc[2 * rr + 1]);
            }
        }
        __syncthreads();
    }

#pragma unroll
    for (int r = 0; r < 32; r++) {
        float2 v = up2(acc[r]);
        *(float2*)&g_wx[(size_t)(row0 + rh * 32 + r) * HH + 2 * cp] = v;
    }
}

// ---------------- Recurrence kernel (split-K-2, 256 threads) ----------------
// One CTA per batch element. Thread pair (2j, 2j+1) owns channel j:
//   p = tid&1 selects K-half [p*64, p*64+64). Each thread does 64 MACs
//   (32 ffma2 over 16 LDS.128 chunks), partner halves merged via shfl.xor 1.
// Odd lanes read chunks in XOR-4 rotated order so the two unique addresses
// per warp LDS.128 land in distinct bank quads (1 phase, no conflict).
// The u registers are loaded in the SAME rotated order so register-array
// indices in the hot loop stay compile-time constants.
template <int LAYER>
__global__ __launch_bounds__(256) void recurrence_k(
    const float* __restrict__ u, const float* __restrict__ bg,
    const float* __restrict__ bu, const float* __restrict__ zeta,
    const float* __restrict__ nu, const float* __restrict__ lambd,
    const float* __restrict__ gamma, float* __restrict__ d_out_full,
    int write_h) {
    const int b = blockIdx.x;
    const int tid = threadIdx.x;
    const int j = tid >> 1;   // channel 0..127
    const int p = tid & 1;    // K-half
    const int rot = p << 2;   // chunk-order rotation for odd lanes

    __shared__ __align__(16) float h_sh[2][HH];

    // u pairs for this thread's K-half, stored in rotated chunk order:
    // iteration c of the hot loop reads h chunk (c ^ rot); ucp[2c],ucp[2c+1]
    // hold the matching u rows.
    unsigned long long ucp[32];
#pragma unroll
    for (int c = 0; c < 16; c++) {
        int cc = c ^ rot;
        int r0 = p * 64 + 4 * cc;  // first of 4 consecutive u-rows in chunk cc
        ucp[2 * c]     = pk2(u[(size_t)(r0 + 0) * HH + j], u[(size_t)(r0 + 1) * HH + j]);
        ucp[2 * c + 1] = pk2(u[(size_t)(r0 + 2) * HH + j], u[(size_t)(r0 + 3) * HH + j]);
    }

    const float bgj = bg[j];
    const float buj = bu[j];
    const float sz = sigmoidf_(zeta[0]);
    const float sn = sigmoidf_(nu[0]);
    const float gcv = fminf(fmaxf(gamma[0], 0.0f), 1.0f);
    const float c1 = (1.0f - gcv) * lambd[0];

    if (p == 0) h_sh[0][j] = 0.0f;
    float h_prev = 0.0f;

    const float* __restrict__ wx = g_wx + (size_t)b * SS * HH + j;
    float* __restrict__ outp =
        (LAYER == 0) ? (g_out0 + (size_t)b * SS * HH + j)
                     : (d_out_full + (size_t)b * SS * HH + j);

    __syncthreads();
    float wx_cur = wx[0];

    for (int t = 0; t < SS; t++) {
        // prefetch next wx behind the matvec
        int tn = (t + 1 < SS) ? (t + 1) : (SS - 1);
        float wx_nxt = wx[(size_t)tn * HH];

        const ulonglong2* hb =
            ((const ulonglong2*)h_sh[t & 1]) + (p << 4);  // this half's base

        unsigned long long a0 = 0ULL, a1 = 0ULL, a2 = 0ULL, a3 = 0ULL;
#pragma unroll
        for (int c = 0; c < 16; c += 2) {
            ulonglong2 v0 = hb[c ^ rot];
            ulonglong2 v1 = hb[(c + 1) ^ rot];
            a0 = ffma2(v0.x, ucp[2 * c], a0);
            a1 = ffma2(v0.y, ucp[2 * c + 1], a1);
            a2 = ffma2(v1.x, ucp[2 * c + 2], a2);
            a3 = ffma2(v1.y, ucp[2 * c + 3], a3);
        }
        unsigned long long s = addx2(addx2(a0, a1), addx2(a2, a3));
        float2 sf = up2(s);
        float part = sf.x + sf.y;
        float pre = part + __shfl_xor_sync(0xffffffffu, part, 1) + wx_cur;

        float z = sigmoidf_(pre + bgj);
        float hh = tanhf_(pre + buj);
        float h_new = z * h_prev + (sz * (1.0f - z) + sn) * hh;
        float ho = fmaf(gcv, h_new, c1);

        if (p) {
            outp[(size_t)t * HH] = ho;          // odd lane: global out
        } else {
            h_sh[(t + 1) & 1][j] = ho;          // even lane: next-step h
        }
        h_prev = ho;
        __syncthreads();
        wx_cur = wx_nxt;
    }

    if (write_h && p == 0) {
        d_out_full[(size_t)BB * SS * HH + (size_t)LAYER * BB * HH + b * HH + j] =
            h_prev;
    }
}

// ---------------- launch ----------------
extern "C" void kernel_launch(void* const* d_in, const int* in_sizes, int n_in,
                              void* d_out, int out_size) {
    const float* x      = (const float*)d_in[0];
    const float* w0     = (const float*)d_in[1];
    const float* u0     = (const float*)d_in[2];
    const float* bg0    = (const float*)d_in[3];
    const float* bu0    = (const float*)d_in[4];
    const float* zeta0  = (const float*)d_in[5];
    const float* nu0    = (const float*)d_in[6];
    const float* lambd0 = (const float*)d_in[7];
    const float* gamma0 = (const float*)d_in[8];
    const float* w1     = (const float*)d_in[9];
    const float* u1     = (const float*)d_in[10];
    const float* bg1    = (const float*)d_in[11];
    const float* bu1    = (const float*)d_in[12];
    const float* zeta1  = (const float*)d_in[13];
    const float* nu1    = (const float*)d_in[14];
    const float* lambd1 = (const float*)d_in[15];
    const float* gamma1 = (const float*)d_in[16];

    float* out = (float*)d_out;
    const int M = BB * SS;
    const int write_h = (out_size >= BB * SS * HH + 2 * BB * HH) ? 1 : 0;

    // wx0 = x @ w0
    gemm_proj<II, false><<<M / 64, 128>>>(x, w0);
    // layer 0 recurrence -> g_out0 (+ h0T)
    recurrence_k<0><<<BB, 256>>>(u0, bg0, bu0, zeta0, nu0, lambd0, gamma0, out,
                                 write_h);
    // wx1 = out0 @ w1
    gemm_proj<HH, true><<<M / 64, 128>>>(nullptr, w1);
    // layer 1 recurrence -> out (+ h1T)
    recurrence_k<1><<<BB, 256>>>(u1, bg1, bu1, zeta1, nu1, lambd1, gamma1, out,
                                 write_h);
}

// round 3
// speedup vs baseline: 1.1495x; 1.1146x over previous
#include <cuda_runtime.h>
#include <cuda_bf16.h>
#include <cstdint>

// Problem constants
#define BB 64
#define SS 2048
#define II 64
#define HH 128

// Scratch (allocation-free rule: __device__ globals)
__device__ float g_wx[BB * SS * HH];  // wx0 = x @ w0

// ---------------- f32x2 helpers ----------------
__device__ __forceinline__ unsigned long long pk2(float lo, float hi) {
    unsigned long long r;
    asm("mov.b64 %0, {%1,%2};" : "=l"(r) : "f"(lo), "f"(hi));
    return r;
}
__device__ __forceinline__ unsigned long long ffma2(unsigned long long a,
                                                    unsigned long long b,
                                                    unsigned long long c) {
    unsigned long long d;
    asm("fma.rn.f32x2 %0, %1, %2, %3;" : "=l"(d) : "l"(a), "l"(b), "l"(c));
    return d;
}
__device__ __forceinline__ unsigned long long addx2(unsigned long long a,
                                                    unsigned long long b) {
    unsigned long long d;
    asm("add.rn.f32x2 %0, %1, %2;" : "=l"(d) : "l"(a), "l"(b));
    return d;
}
__device__ __forceinline__ float2 up2(unsigned long long v) {
    float2 f;
    asm("mov.b64 {%0,%1}, %2;" : "=f"(f.x), "=f"(f.y) : "l"(v));
    return f;
}

__device__ __forceinline__ float sigmoidf_(float x) {
    return __fdividef(1.0f, 1.0f + __expf(-x));
}
__device__ __forceinline__ float tanhf_(float x) {
    return 1.0f - __fdividef(2.0f, __expf(2.0f * x) + 1.0f);
}

// Full 128-MAC dot: h (SMEM broadcast) . column (64 packed f32x2 registers).
// 8 independent accumulator chains of depth 8.
__device__ __forceinline__ float dot128(const float* hbf,
                                        const unsigned long long* cc) {
    const ulonglong2* hb = (const ulonglong2*)hbf;
    unsigned long long a0 = 0, a1 = 0, a2 = 0, a3 = 0, a4 = 0, a5 = 0, a6 = 0,
                       a7 = 0;
#pragma unroll
    for (int c = 0; c < 32; c += 4) {
        ulonglong2 v0 = hb[c];
        ulonglong2 v1 = hb[c + 1];
        ulonglong2 v2 = hb[c + 2];
        ulonglong2 v3 = hb[c + 3];
        a0 = ffma2(v0.x, cc[2 * c + 0], a0);
        a1 = ffma2(v0.y, cc[2 * c + 1], a1);
        a2 = ffma2(v1.x, cc[2 * c + 2], a2);
        a3 = ffma2(v1.y, cc[2 * c + 3], a3);
        a4 = ffma2(v2.x, cc[2 * c + 4], a4);
        a5 = ffma2(v2.y, cc[2 * c + 5], a5);
        a6 = ffma2(v3.x, cc[2 * c + 6], a6);
        a7 = ffma2(v3.y, cc[2 * c + 7], a7);
    }
    unsigned long long s = addx2(addx2(addx2(a0, a1), addx2(a2, a3)),
                                 addx2(addx2(a4, a5), addx2(a6, a7)));
    float2 f = up2(s);
    return f.x + f.y;
}

// ---------------- GEMM: g_wx[M,128] = x[M,64] @ w0[64,128] ----------------
__global__ __launch_bounds__(128) void gemm_proj(const float* __restrict__ A,
                                                 const float* __restrict__ W) {
    constexpr int K = II;
    constexpr int KC = 32;
    __shared__ unsigned long long ATd[KC][66];
    __shared__ float Wsh[KC][HH];

    const int tid = threadIdx.x;
    const int row0 = blockIdx.x * 64;
    const int cp = tid & 63;
    const int rh = tid >> 6;

    unsigned long long acc[32];
#pragma unroll
    for (int i = 0; i < 32; i++) acc[i] = 0ULL;

    for (int k0 = 0; k0 < K; k0 += KC) {
#pragma unroll
        for (int i = 0; i < 16; i++) {
            int idx = tid + i * 128;
            int r = idx >> 5, k = idx & 31;
            float a = A[(size_t)(row0 + r) * K + (k0 + k)];
            ATd[k][r] = pk2(a, a);
        }
#pragma unroll
        for (int i = 0; i < 32; i++) {
            int idx = tid + i * 128;
            int k = idx >> 7, c = idx & 127;
            Wsh[k][c] = W[(size_t)(k0 + k) * HH + c];
        }
        __syncthreads();

#pragma unroll 4
        for (int k = 0; k < KC; k++) {
            float2 wv = *(const float2*)&Wsh[k][2 * cp];
            unsigned long long w2 = pk2(wv.x, wv.y);
            const unsigned long long* arow = &ATd[k][rh * 32];
#pragma unroll
            for (int rr = 0; rr < 16; rr++) {
                ulonglong2 av = *(const ulonglong2*)(arow + 2 * rr);
                acc[2 * rr] = ffma2(av.x, w2, acc[2 * rr]);
                acc[2 * rr + 1] = ffma2(av.y, w2, acc[2 * rr + 1]);
            }
        }
        __syncthreads();
    }

#pragma unroll
    for (int r = 0; r < 32; r++) {
        float2 v = up2(acc[r]);
        *(float2*)&g_wx[(size_t)(row0 + rh * 32 + r) * HH + 2 * cp] = v;
    }
}

// ---------------- Fused 2-layer pipelined recurrence ----------------
// One CTA per batch. 384 threads = 3 warpgroups of 128 (thread j = channel j):
//   WG0: layer-0 step i        (reads h0[i-1], wx0[i];  writes h0[i])
//   WG1: wx1[i-1] = h0[i-1]@w1 (reads h0[i-1];          writes wx1[i-1])
//   WG2: layer-1 step t=i-2    (reads h1[t-1], wx1[t];  writes h1[t], out1[t])
// The 2-step lag makes the three streams independent within an iteration;
// one __syncthreads per iteration. Each SMSP carries one warp of each WG,
// so stalls in one stream are hidden by the other two.
__global__ __launch_bounds__(384) void fused_recurrence(
    const float* __restrict__ u0, const float* __restrict__ bg0,
    const float* __restrict__ bu0, const float* __restrict__ zeta0,
    const float* __restrict__ nu0, const float* __restrict__ lambd0,
    const float* __restrict__ gamma0, const float* __restrict__ w1,
    const float* __restrict__ u1, const float* __restrict__ bg1,
    const float* __restrict__ bu1, const float* __restrict__ zeta1,
    const float* __restrict__ nu1, const float* __restrict__ lambd1,
    const float* __restrict__ gamma1, float* __restrict__ out, int write_h) {
    const int b = blockIdx.x;
    const int tid = threadIdx.x;
    const int wg = tid >> 7;   // 0,1,2
    const int j = tid & 127;   // channel

    __shared__ __align__(16) float h0_sh[2][HH];
    __shared__ __align__(16) float wx1_sh[2][HH];
    __shared__ __align__(16) float h1_sh[2][HH];

    // This WG's matrix column in 64 packed f32x2 registers.
    const float* __restrict__ M = (wg == 0) ? u0 : (wg == 1) ? w1 : u1;
    unsigned long long cc[64];
#pragma unroll
    for (int m = 0; m < 64; m++)
        cc[m] = pk2(M[(size_t)(2 * m) * HH + j], M[(size_t)(2 * m + 1) * HH + j]);

    // Per-WG scalars
    float bgj = 0.f, buj = 0.f, sz = 0.f, sn = 0.f, gcv = 0.f, c1 = 0.f;
    if (wg == 0) {
        bgj = bg0[j]; buj = bu0[j];
        sz = sigmoidf_(zeta0[0]); sn = sigmoidf_(nu0[0]);
        gcv = fminf(fmaxf(gamma0[0], 0.0f), 1.0f);
        c1 = (1.0f - gcv) * lambd0[0];
    } else if (wg == 2) {
        bgj = bg1[j]; buj = bu1[j];
        sz = sigmoidf_(zeta1[0]); sn = sigmoidf_(nu1[0]);
        gcv = fminf(fmaxf(gamma1[0], 0.0f), 1.0f);
        c1 = (1.0f - gcv) * lambd1[0];
    }

    // Init: h0 at step -1 lives in slot 1; h1 at step -1 in slot 1.
    if (wg == 0) h0_sh[1][j] = 0.0f;
    if (wg == 2) h1_sh[1][j] = 0.0f;

    float h_prev = 0.0f;  // own-channel previous h (WG0: h0, WG2: h1)

    const float* __restrict__ wx0p = g_wx + (size_t)b * SS * HH + j;
    float* __restrict__ outp = out + (size_t)b * SS * HH + j;

    __syncthreads();
    float wx_cur = (wg == 0) ? wx0p[0] : 0.0f;

    for (int i = 0; i < SS + 2; i++) {
        if (wg == 0) {
            if (i < SS) {
                float wx_nxt = (i + 1 < SS) ? wx0p[(size_t)(i + 1) * HH] : 0.0f;
                float pre = dot128(h0_sh[(i + 1) & 1], cc) + wx_cur;
                float z = sigmoidf_(pre + bgj);
                float hh = tanhf_(pre + buj);
                float h_new = z * h_prev + (sz * (1.0f - z) + sn) * hh;
                float ho = fmaf(gcv, h_new, c1);
                h0_sh[i & 1][j] = ho;
                h_prev = ho;
                wx_cur = wx_nxt;
            }
        } else if (wg == 1) {
            if (i >= 1 && i <= SS) {
                wx1_sh[(i - 1) & 1][j] = dot128(h0_sh[(i - 1) & 1], cc);
            }
        } else {
            if (i >= 2) {
                int t = i - 2;
                float pre = dot128(h1_sh[(t + 1) & 1], cc) + wx1_sh[t & 1][j];
                float z = sigmoidf_(pre + bgj);
                float hh = tanhf_(pre + buj);
                float h_new = z * h_prev + (sz * (1.0f - z) + sn) * hh;
                float ho = fmaf(gcv, h_new, c1);
                h1_sh[t & 1][j] = ho;
                outp[(size_t)t * HH] = ho;
                h_prev = ho;
            }
        }
        __syncthreads();
    }

    if (write_h) {
        if (wg == 0)
            out[(size_t)BB * SS * HH + (size_t)b * HH + j] = h_prev;  // h0T
        else if (wg == 2)
            out[(size_t)BB * SS * HH + (size_t)BB * HH + (size_t)b * HH + j] =
                h_prev;  // h1T
    }
}

// ---------------- launch ----------------
extern "C" void kernel_launch(void* const* d_in, const int* in_sizes, int n_in,
                              void* d_out, int out_size) {
    const float* x      = (const float*)d_in[0];
    const float* w0     = (const float*)d_in[1];
    const float* u0     = (const float*)d_in[2];
    const float* bg0    = (const float*)d_in[3];
    const float* bu0    = (const float*)d_in[4];
    const float* zeta0  = (const float*)d_in[5];
    const float* nu0    = (const float*)d_in[6];
    const float* lambd0 = (const float*)d_in[7];
    const float* gamma0 = (const float*)d_in[8];
    const float* w1     = (const float*)d_in[9];
    const float* u1     = (const float*)d_in[10];
    const float* bg1    = (const float*)d_in[11];
    const float* bu1    = (const float*)d_in[12];
    const float* zeta1  = (const float*)d_in[13];
    const float* nu1    = (const float*)d_in[14];
    const float* lambd1 = (const float*)d_in[15];
    const float* gamma1 = (const float*)d_in[16];

    float* out = (float*)d_out;
    const int M = BB * SS;
    const int write_h = (out_size >= BB * SS * HH + 2 * BB * HH) ? 1 : 0;

    // wx0 = x @ w0
    gemm_proj<<<M / 64, 128>>>(x, w0);
    // fused: layer0 + (out0 @ w1) + layer1, software-pipelined
    fused_recurrence<<<BB, 384>>>(u0, bg0, bu0, zeta0, nu0, lambd0, gamma0, w1,
                                  u1, bg1, bu1, zeta1, nu1, lambd1, gamma1, out,
                                  write_h);
}

// round 5
// speedup vs baseline: 1.1875x; 1.0330x over previous
#include <cuda_runtime.h>
#include <cuda_bf16.h>
#include <cstdint>

// Problem constants
#define BB 64
#define SS 2048
#define II 64
#define HH 128

// Scratch (allocation-free rule: __device__ globals)
__device__ float g_wx[BB * SS * HH];  // wx0 = x @ w0

// ---------------- f32x2 helpers ----------------
__device__ __forceinline__ unsigned long long pk2(float lo, float hi) {
    unsigned long long r;
    asm("mov.b64 %0, {%1,%2};" : "=l"(r) : "f"(lo), "f"(hi));
    return r;
}
__device__ __forceinline__ unsigned long long ffma2(unsigned long long a,
                                                    unsigned long long b,
                                                    unsigned long long c) {
    unsigned long long d;
    asm("fma.rn.f32x2 %0, %1, %2, %3;" : "=l"(d) : "l"(a), "l"(b), "l"(c));
    return d;
}
__device__ __forceinline__ unsigned long long addx2(unsigned long long a,
                                                    unsigned long long b) {
    unsigned long long d;
    asm("add.rn.f32x2 %0, %1, %2;" : "=l"(d) : "l"(a), "l"(b));
    return d;
}
__device__ __forceinline__ float2 up2(unsigned long long v) {
    float2 f;
    asm("mov.b64 {%0,%1}, %2;" : "=f"(f.x), "=f"(f.y) : "l"(v));
    return f;
}

__device__ __forceinline__ float sigmoidf_(float x) {
    return __fdividef(1.0f, 1.0f + __expf(-x));
}
__device__ __forceinline__ float tanhf_(float x) {
    return 1.0f - __fdividef(2.0f, __expf(2.0f * x) + 1.0f);
}

// Named barriers: 1 = WG0+WG1 (h0 ring), 2 = WG1+WG2 (wx1 + h1 rings)
#define BAR1() asm volatile("bar.sync 1, 256;" ::: "memory")
#define BAR2() asm volatile("bar.sync 2, 256;" ::: "memory")

// Full 128-MAC dot with explicit 4-deep LDS pipeline.
// h (SMEM, warp-uniform broadcast) . column (64 packed f32x2 registers).
__device__ __forceinline__ float dot128p(const float* hbf,
                                         const unsigned long long* cc) {
    const ulonglong2* hb = (const ulonglong2*)hbf;
    ulonglong2 buf[4];
#pragma unroll
    for (int k = 0; k < 4; k++) buf[k] = hb[k];
    unsigned long long a0 = 0, a1 = 0, a2 = 0, a3 = 0;
#pragma unroll
    for (int c = 0; c < 32; c++) {
        ulonglong2 v = buf[c & 3];
        if (c + 4 < 32) buf[c & 3] = hb[c + 4];
        if (c & 1) {
            a2 = ffma2(v.x, cc[2 * c + 0], a2);
            a3 = ffma2(v.y, cc[2 * c + 1], a3);
        } else {
            a0 = ffma2(v.x, cc[2 * c + 0], a0);
            a1 = ffma2(v.y, cc[2 * c + 1], a1);
        }
    }
    unsigned long long s = addx2(addx2(a0, a1), addx2(a2, a3));
    float2 f = up2(s);
    return f.x + f.y;
}

// ---------------- GEMM: g_wx[M,128] = x[M,64] @ w0[64,128] ----------------
__global__ __launch_bounds__(128) void gemm_proj(const float* __restrict__ A,
                                                 const float* __restrict__ W) {
    constexpr int K = II;
    constexpr int KC = 32;
    __shared__ unsigned long long ATd[KC][66];
    __shared__ float Wsh[KC][HH];

    const int tid = threadIdx.x;
    const int row0 = blockIdx.x * 64;
    const int cp = tid & 63;
    const int rh = tid >> 6;

    unsigned long long acc[32];
#pragma unroll
    for (int i = 0; i < 32; i++) acc[i] = 0ULL;

    for (int k0 = 0; k0 < K; k0 += KC) {
#pragma unroll
        for (int i = 0; i < 16; i++) {
            int idx = tid + i * 128;
            int r = idx >> 5, k = idx & 31;
            float a = A[(size_t)(row0 + r) * K + (k0 + k)];
            ATd[k][r] = pk2(a, a);
        }
#pragma unroll
        for (int i = 0; i < 32; i++) {
            int idx = tid + i * 128;
            int k = idx >> 7, c = idx & 127;
            Wsh[k][c] = W[(size_t)(k0 + k) * HH + c];
        }
        __syncthreads();

#pragma unroll 4
        for (int k = 0; k < KC; k++) {
            float2 wv = *(const float2*)&Wsh[k][2 * cp];
            unsigned long long w2 = pk2(wv.x, wv.y);
            const unsigned long long* arow = &ATd[k][rh * 32];
#pragma unroll
            for (int rr = 0; rr < 16; rr++) {
                ulonglong2 av = *(const ulonglong2*)(arow + 2 * rr);
                acc[2 * rr] = ffma2(av.x, w2, acc[2 * rr]);
                acc[2 * rr + 1] = ffma2(av.y, w2, acc[2 * rr + 1]);
            }
        }
        __syncthreads();
    }

#pragma unroll
    for (int r = 0; r < 32; r++) {
        float2 v = up2(acc[r]);
        *(float2*)&g_wx[(size_t)(row0 + rh * 32 + r) * HH + 2 * cp] = v;
    }
}

// ---------------- Fused 2-layer pipelined recurrence ----------------
// One CTA per batch. 384 threads = 3 warpgroups of 128 (thread j = channel j):
//   WG0: layer-0 step i        — syncs on named bar 1 (with WG1)
//   WG1: wx1[i-1] = h0[i-1]@w1 — syncs on bars 1 and 2
//   WG2: layer-1 step t=i-2    — syncs on named bar 2 (with WG1)
// Named barriers replace the CTA-wide __syncthreads so WG0 and WG2 are not
// phase-locked to each other; warps on an SMSP drift and hide each other's
// latency.
__global__ __launch_bounds__(384) void fused_recurrence(
    const float* __restrict__ u0, const float* __restrict__ bg0,
    const float* __restrict__ bu0, const float* __restrict__ zeta0,
    const float* __restrict__ nu0, const float* __restrict__ lambd0,
    const float* __restrict__ gamma0, const float* __restrict__ w1,
    const float* __restrict__ u1, const float* __restrict__ bg1,
    const float* __restrict__ bu1, const float* __restrict__ zeta1,
    const float* __restrict__ nu1, const float* __restrict__ lambd1,
    const float* __restrict__ gamma1, float* __restrict__ out, int write_h) {
    const int b = blockIdx.x;
    const int tid = threadIdx.x;
    const int wg = tid >> 7;   // 0,1,2
    const int j = tid & 127;   // channel

    __shared__ __align__(16) float h0_sh[2][HH];
    __shared__ __align__(16) float wx1_sh[2][HH];
    __shared__ __align__(16) float h1_sh[2][HH];

    // This WG's matrix column in 64 packed f32x2 registers.
    const float* __restrict__ M = (wg == 0) ? u0 : (wg == 1) ? w1 : u1;
    unsigned long long cc[64];
#pragma unroll
    for (int m = 0; m < 64; m++)
        cc[m] = pk2(M[(size_t)(2 * m) * HH + j], M[(size_t)(2 * m + 1) * HH + j]);

    // Per-WG scalars
    float bgj = 0.f, buj = 0.f, szn = 0.f, sz = 0.f, gcv = 0.f, c1 = 0.f;
    if (wg == 0) {
        bgj = bg0[j]; buj = bu0[j];
        sz = sigmoidf_(zeta0[0]);
        szn = sz + sigmoidf_(nu0[0]);
        gcv = fminf(fmaxf(gamma0[0], 0.0f), 1.0f);
        c1 = (1.0f - gcv) * lambd0[0];
    } else if (wg == 2) {
        bgj = bg1[j]; buj = bu1[j];
        sz = sigmoidf_(zeta1[0]);
        szn = sz + sigmoidf_(nu1[0]);
        gcv = fminf(fmaxf(gamma1[0], 0.0f), 1.0f);
        c1 = (1.0f - gcv) * lambd1[0];
    }

    if (wg == 0) h0_sh[1][j] = 0.0f;
    if (wg == 2) h1_sh[1][j] = 0.0f;

    float h_prev = 0.0f;  // own-channel previous h (WG0: h0, WG2: h1)

    const float* __restrict__ wx0p = g_wx + (size_t)b * SS * HH + j;
    float* __restrict__ outp = out + (size_t)b * SS * HH + j;

    __syncthreads();  // once: initial state visible to everyone

    float wx_cur = (wg == 0) ? wx0p[0] : 0.0f;

    if (wg == 0) {
        for (int i = 0; i < SS + 2; i++) {
            if (i < SS) {
                int tn = (i + 1 < SS) ? (i + 1) : (SS - 1);
                float wx_nxt = wx0p[(size_t)tn * HH];
                float pre = dot128p(h0_sh[(i + 1) & 1], cc) + wx_cur;
                float z = sigmoidf_(pre + bgj);
                float hh = tanhf_(pre + buj);
                float coef = fmaf(-sz, z, szn);
                float h_new = fmaf(z, h_prev, coef * hh);
                float ho = fmaf(gcv, h_new, c1);
                h0_sh[i & 1][j] = ho;
                h_prev = ho;
                wx_cur = wx_nxt;
            }
            BAR1();
        }
    } else if (wg == 1) {
        for (int i = 0; i < SS + 2; i++) {
            if (i >= 1 && i <= SS) {
                wx1_sh[(i - 1) & 1][j] = dot128p(h0_sh[(i - 1) & 1], cc);
            }
            BAR1();
            BAR2();
        }
    } else {
        for (int i = 0; i < SS + 2; i++) {
            if (i >= 2) {
                int t = i - 2;
                float pre = dot128p(h1_sh[(t + 1) & 1], cc) + wx1_sh[t & 1][j];
                float z = sigmoidf_(pre + bgj);
                float hh = tanhf_(pre + buj);
                float coef = fmaf(-sz, z, szn);
                float h_new = fmaf(z, h_prev, coef * hh);
                float ho = fmaf(gcv, h_new, c1);
                h1_sh[t & 1][j] = ho;
                *outp = ho;
                outp += HH;
                h_prev = ho;
            }
            BAR2();
        }
    }

    if (write_h) {
        if (wg == 0)
            out[(size_t)BB * SS * HH + (size_t)b * HH + j] = h_prev;  // h0T
        else if (wg == 2)
            out[(size_t)BB * SS * HH + (size_t)BB * HH + (size_t)b * HH + j] =
                h_prev;  // h1T
    }
}

// ---------------- launch ----------------
extern "C" void kernel_launch(void* const* d_in, const int* in_sizes, int n_in,
                              void* d_out, int out_size) {
    const float* x      = (const float*)d_in[0];
    const float* w0     = (const float*)d_in[1];
    const float* u0     = (const float*)d_in[2];
    const float* bg0    = (const float*)d_in[3];
    const float* bu0    = (const float*)d_in[4];
    const float* zeta0  = (const float*)d_in[5];
    const float* nu0    = (const float*)d_in[6];
    const float* lambd0 = (const float*)d_in[7];
    const float* gamma0 = (const float*)d_in[8];
    const float* w1     = (const float*)d_in[9];
    const float* u1     = (const float*)d_in[10];
    const float* bg1    = (const float*)d_in[11];
    const float* bu1    = (const float*)d_in[12];
    const float* zeta1  = (const float*)d_in[13];
    const float* nu1    = (const float*)d_in[14];
    const float* lambd1 = (const float*)d_in[15];
    const float* gamma1 = (const float*)d_in[16];

    float* out = (float*)d_out;
    const int M = BB * SS;
    const int write_h = (out_size >= BB * SS * HH + 2 * BB * HH) ? 1 : 0;

    // wx0 = x @ w0
    gemm_proj<<<M / 64, 128>>>(x, w0);
    // fused: layer0 + (out0 @ w1) + layer1, software-pipelined, named barriers
    fused_recurrence<<<BB, 384>>>(u0, bg0, bu0, zeta0, nu0, lambd0, gamma0, w1,
                                  u1, bg1, bu1, zeta1, nu1, lambd1, gamma1, out,
                                  write_h);
}